// round 15
// baseline (speedup 1.0000x reference)
#include <cuda_runtime.h>
#include <cstdint>
#include <math.h>

// Problem constants (dataset: B=65536, D=256, K=10)
#define KK 10
#define DD 256
#define NBLK 740              // 5 blocks/SM
#define L2PI_F 1.8378770664093453f
#define MARGIN 0.02f

typedef unsigned long long ull;

// ---------- packed f32x2 helpers ----------
static __device__ __forceinline__ ull pack2(float x, float y) {
    ull r; asm("mov.b64 %0, {%1, %2};" : "=l"(r) : "f"(x), "f"(y)); return r;
}
static __device__ __forceinline__ void unpack2(ull v, float& x, float& y) {
    asm("mov.b64 {%0, %1}, %2;" : "=f"(x), "=f"(y) : "l"(v));
}
static __device__ __forceinline__ ull fma2(ull a, ull b, ull c) {
    ull d; asm("fma.rn.f32x2 %0, %1, %2, %3;" : "=l"(d) : "l"(a), "l"(b), "l"(c)); return d;
}
static __device__ __forceinline__ ull add2(ull a, ull b) {
    ull d; asm("add.rn.f32x2 %0, %1, %2;" : "=l"(d) : "l"(a), "l"(b)); return d;
}
static __device__ __forceinline__ ull mul2(ull a, ull b) {
    ull d; asm("mul.rn.f32x2 %0, %1, %2;" : "=l"(d) : "l"(a), "l"(b)); return d;
}

// ---- warp-collective exact fix for one row (bitwise XLA:GPU order, proven r11-14) ----
static __device__ __forceinline__ void fix_row(
    int rr, int lane, ull* sq, const ull* s_nm,
    const float* __restrict__ q, const float* __restrict__ lv,
    int fast, float logk, ull L2,
    float* out_logit, float* out_qy, float* out_ind)
{
    const int kk = (lane < 20) ? (lane >> 1) : 0;
    const int h  = lane & 1;

    {   // stage row q: coalesced, 2 float4 per lane
        const float4* q4 = reinterpret_cast<const float4*>(q + (size_t)rr * DD);
        float4 v0 = __ldg(q4 + lane);
        float4 v1 = __ldg(q4 + lane + 32);
        sq[2 * lane]            = pack2(v0.x, v0.y);
        sq[2 * lane + 1]        = pack2(v0.z, v0.w);
        sq[2 * (lane + 32)]     = pack2(v1.x, v1.y);
        sq[2 * (lane + 32) + 1] = pack2(v1.z, v1.w);
    }
    __syncwarp();

    float Wv[2];
    #pragma unroll
    for (int t2 = 0; t2 < 2; t2++) {
        const int w4 = h + 2 * t2;
        float a[16];
        if (fast) {
            #pragma unroll
            for (int l = 0; l < 16; l++) {
                int p1 = w4 * 32 + l, p2 = p1 + 16;
                ull f1 = add2(sq[p1], s_nm[p1 * KK + kk]);   // fl(q-mu)
                ull u1 = add2(mul2(f1, f1), L2);             // fl(fl(d^2)+L2PI)
                ull f2 = add2(sq[p2], s_nm[p2 * KK + kk]);
                ull u2 = add2(mul2(f2, f2), L2);
                float x1, y1, x2, y2;
                unpack2(u1, x1, y1); unpack2(u2, x2, y2);
                // a_l = fl( s_l + s_{l+16} ), s = fl(u_even + u_odd)
                a[l] = __fadd_rn(__fadd_rn(x1, y1), __fadd_rn(x2, y2));
            }
        } else {
            #pragma unroll
            for (int l = 0; l < 16; l++) {
                float s12[2];
                #pragma unroll
                for (int hh = 0; hh < 2; hh++) {
                    int p = w4 * 32 + l + 16 * hh;
                    float q0, q1, n0, n1;
                    unpack2(sq[p], q0, q1);
                    unpack2(s_nm[p * KK + kk], n0, n1);
                    float v0 = __ldg(&lv[kk * DD + 2 * p]);
                    float v1 = __ldg(&lv[kk * DD + 2 * p + 1]);
                    float e0 = (v0 == 0.0f) ? 1.0f : expf(v0);
                    float e1 = (v1 == 0.0f) ? 1.0f : expf(v1);
                    float f0 = __fadd_rn(q0, n0), f1 = __fadd_rn(q1, n1);
                    float u0 = __fadd_rn(__fadd_rn(
                        __fdiv_rn(__fmul_rn(f0, f0), e0), v0), L2PI_F);
                    float u1 = __fadd_rn(__fadd_rn(
                        __fdiv_rn(__fmul_rn(f1, f1), e1), v1), L2PI_F);
                    s12[hh] = __fadd_rn(u0, u1);
                }
                a[l] = __fadd_rn(s12[0], s12[1]);
            }
        }
        float bb[8];
        #pragma unroll
        for (int l = 0; l < 8; l++) bb[l] = __fadd_rn(a[l], a[l + 8]);
        float cc[4];
        #pragma unroll
        for (int l = 0; l < 4; l++) cc[l] = __fadd_rn(bb[l], bb[l + 4]);
        float d0 = __fadd_rn(cc[0], cc[2]);
        float d1 = __fadd_rn(cc[1], cc[3]);
        Wv[t2] = __fadd_rn(d0, d1);
    }
    float sum2 = __fadd_rn(Wv[0], Wv[1]);              // h=0: W0+W2 ; h=1: W1+W3
    float s_other = __shfl_down_sync(0xffffffffu, sum2, 1);
    float L = __fadd_rn(sum2, s_other);                // valid at even lanes
    float lgt = __fadd_rn(__fmul_rn(-0.5f, L), logk);

    float l10[KK];
    #pragma unroll
    for (int k = 0; k < KK; k++)
        l10[k] = __shfl_sync(0xffffffffu, lgt, 2 * k);

    if (lane == 0) {
        float m = l10[0];
        #pragma unroll
        for (int k = 1; k < KK; k++) m = fmaxf(m, l10[k]);
        float e[KK];
        #pragma unroll
        for (int k = 0; k < KK; k++) e[k] = expf(__fadd_rn(l10[k], -m));
        float s0 = __fadd_rn(__fadd_rn(__fadd_rn(e[0], e[8]), e[4]),
                             __fadd_rn(e[2], e[6]));
        float s1 = __fadd_rn(__fadd_rn(__fadd_rn(e[1], e[9]), e[5]),
                             __fadd_rn(e[3], e[7]));
        float ssum = __fadd_rn(s0, s1);
        float qv[KK];
        #pragma unroll
        for (int k = 0; k < KK; k++) qv[k] = __fdiv_rn(e[k], ssum);
        #pragma unroll
        for (int k = 0; k < KK; k++) {
            out_logit[(size_t)rr * KK + k] = l10[k];
            out_qy   [(size_t)rr * KK + k] = qv[k];
        }
        int best = 0; float bv = qv[0];
        #pragma unroll
        for (int k = 1; k < KK; k++)
            if (qv[k] > bv) { bv = qv[k]; best = k; }
        out_ind[rr] = (float)best;
    }
    __syncwarp();
}

// ============ single kernel: 8 lanes/row, full-line LDG, 1-phase coef LDS ============
__global__ void __launch_bounds__(128, 5)
k_all(const float* __restrict__ q, const float* __restrict__ mu,
      const float* __restrict__ lv,
      float* __restrict__ out_logit, float* __restrict__ out_qy,
      float* __restrict__ out_ind, int nrows)
{
    // coef: idx (g*10+k)*8 + s -> {pack2(cb[d0],cb[d0+1]), pack2(cb[d0+2],cb[d0+3])},
    // d0 = 32g + 4s. Per-(g,k) LDS.128 spans 128B contiguous -> 1 phase, 4-grp broadcast.
    __shared__ __align__(16) ulonglong2 s_cb2[640];     // 10240 B
    __shared__ __align__(16) ull s_nm[128 * KK];        // 10240 B (fix path, p*KK+k)
    __shared__ __align__(16) ull s_q[4][128];           // 4096 B (fix staging, 1/warp)
    __shared__ float s_Cpart[KK][8];
    __shared__ float s_C[KK];
    __shared__ int   s_nz;

    const int t = threadIdx.x;
    const int lane = t & 31, warp = t >> 5;
    if (t == 0) s_nz = 0;
    __syncthreads();

    // ---------- block prep ----------
    #pragma unroll
    for (int i = 0; i < 5; i++) {
        int e = t + 128 * i;                 // 0..639
        int ss = e & 7;
        int gk = e >> 3;
        int k  = gk % 10;
        int g  = gk / 10;
        int d0 = 32 * g + 4 * ss;
        float c[4];
        #pragma unroll
        for (int j = 0; j < 4; j++) {
            float l = lv[k * DD + d0 + j], m = mu[k * DD + d0 + j];
            c[j] = -2.0f * __expf(-l) * m;
        }
        ulonglong2 u;
        u.x = pack2(c[0], c[1]);
        u.y = pack2(c[2], c[3]);
        s_cb2[e] = u;
    }
    int any = 0;
    #pragma unroll
    for (int i = 0; i < KK; i++) {
        int ix = t + 128 * i;
        int p = ix / KK, k = ix % KK, d = 2 * p;
        s_nm[p * KK + k] = pack2(-mu[k * DD + d], -mu[k * DD + d + 1]);
        float l0 = lv[k * DD + d], l1 = lv[k * DD + d + 1];
        if (l0 != 0.0f || l1 != 0.0f) any = 1;
    }
    if (any) atomicOr(&s_nz, 1);
    if (t < 80) {
        int k = t >> 3, part = t & 7;
        float s = 0.0f;
        #pragma unroll 4
        for (int j = 0; j < 32; j++) {
            int d = part * 32 + j;
            float l = lv[k * DD + d], m = mu[k * DD + d];
            s += __fmaf_rn(__expf(-l) * m, m, l) + L2PI_F;
        }
        s_Cpart[k][part] = s;
    }
    __syncthreads();
    if (t < KK) {
        float tot = 0.0f;
        #pragma unroll
        for (int j = 0; j < 8; j++) tot += s_Cpart[t][j];
        float logk0 = (float)log((double)(1.0f / (float)KK));
        s_C[t] = __fmaf_rn(-0.5f, tot, logk0);
    }
    __syncthreads();
    const int fast = (s_nz == 0);
    const float logk = (float)log((double)(1.0f / (float)KK));
    const ull L2 = pack2(L2PI_F, L2PI_F);

    const int s   = lane & 7;        // 16B granule within 128B line
    const int grp = lane >> 3;       // row within 4-row slice
    const int gw  = blockIdx.x * 4 + warp;
    const int nw  = NBLK * 4;
    const int nunits = (nrows + 7) / 8;   // 8 rows per unit (2 slices)

    for (int c = gw; c < nunits; c += nw) {
        const int base = c * 8;
        const int rA = base + grp;           // slice j=0
        const int rB = base + 4 + grp;       // slice j=1
        const float4* qpA = reinterpret_cast<const float4*>(q)
                          + (size_t)((rA < nrows) ? rA : 0) * 64 + s;
        const float4* qpB = reinterpret_cast<const float4*>(q)
                          + (size_t)((rB < nrows) ? rB : 0) * 64 + s;

        ull accA[KK], accB[KK];
        #pragma unroll
        for (int k = 0; k < KK; k++) { accA[k] = 0ull; accB[k] = 0ull; }
        ull S2A = 0ull, S2B = 0ull;

        // depth-2 prefetch; each LDG.128 covers 4 full 128B lines (4 rows)
        float4 bufA[2], bufB[2];
        bufA[0] = __ldg(qpA);     bufB[0] = __ldg(qpB);
        bufA[1] = __ldg(qpA + 8); bufB[1] = __ldg(qpB + 8);

        #pragma unroll
        for (int g = 0; g < 8; g++) {
            float4 vA = bufA[g & 1], vB = bufB[g & 1];
            if (g + 2 < 8) {
                bufA[g & 1] = __ldg(qpA + 8 * (g + 2));
                bufB[g & 1] = __ldg(qpB + 8 * (g + 2));
            }
            ull qa0 = pack2(vA.x, vA.y), qa1 = pack2(vA.z, vA.w);
            ull qb0 = pack2(vB.x, vB.y), qb1 = pack2(vB.z, vB.w);
            S2A = fma2(qa0, qa0, S2A); S2A = fma2(qa1, qa1, S2A);
            S2B = fma2(qb0, qb0, S2B); S2B = fma2(qb1, qb1, S2B);
            const int cb = g * 80 + s;                 // (g*10+k)*8+s
            #pragma unroll
            for (int k = 0; k < KK; k++) {
                ulonglong2 cf = s_cb2[cb + 8 * k];     // 128B-span LDS.128, 1 phase
                accA[k] = fma2(cf.x, qa0, accA[k]);
                accA[k] = fma2(cf.y, qa1, accA[k]);
                accB[k] = fma2(cf.x, qb0, accB[k]);
                accB[k] = fma2(cf.y, qb1, accB[k]);
            }
        }

        // reduce across the 8 sub-lanes of each row (offsets 1, 2, 4)
        #pragma unroll
        for (int k = 0; k < KK; k++) {
            accA[k] = add2(accA[k], __shfl_xor_sync(0xffffffffu, accA[k], 1));
            accA[k] = add2(accA[k], __shfl_xor_sync(0xffffffffu, accA[k], 2));
            accA[k] = add2(accA[k], __shfl_xor_sync(0xffffffffu, accA[k], 4));
            accB[k] = add2(accB[k], __shfl_xor_sync(0xffffffffu, accB[k], 1));
            accB[k] = add2(accB[k], __shfl_xor_sync(0xffffffffu, accB[k], 2));
            accB[k] = add2(accB[k], __shfl_xor_sync(0xffffffffu, accB[k], 4));
        }
        S2A = add2(S2A, __shfl_xor_sync(0xffffffffu, S2A, 1));
        S2A = add2(S2A, __shfl_xor_sync(0xffffffffu, S2A, 2));
        S2A = add2(S2A, __shfl_xor_sync(0xffffffffu, S2A, 4));
        S2B = add2(S2B, __shfl_xor_sync(0xffffffffu, S2B, 1));
        S2B = add2(S2B, __shfl_xor_sync(0xffffffffu, S2B, 2));
        S2B = add2(S2B, __shfl_xor_sync(0xffffffffu, S2B, 4));

        // ---- cheap finish on s==0 lanes (lanes 0,8,16,24); flag near-ties ----
        int needA = 0, needB = 0;
        if (s == 0) {
            #pragma unroll
            for (int j = 0; j < 2; j++) {
                const int row = (j == 0) ? rA : rB;
                if (row < nrows) {
                    const ull* acc = (j == 0) ? accA : accB;
                    ull S2v = (j == 0) ? S2A : S2B;
                    float s2f;
                    { float lo, hi; unpack2(S2v, lo, hi); s2f = lo + hi; }
                    float l[KK];
                    #pragma unroll
                    for (int k = 0; k < KK; k++) {
                        float lo, hi; unpack2(acc[k], lo, hi);
                        l[k] = __fmaf_rn(-0.5f, (lo + hi) + s2f, s_C[k]);
                    }
                    float t1 = l[0], t2 = -3.4e38f;
                    #pragma unroll
                    for (int k = 1; k < KK; k++) {
                        float v = l[k];
                        if (v > t1) { t2 = t1; t1 = v; } else if (v > t2) t2 = v;
                    }
                    float e[KK], ssum = 0.0f;
                    #pragma unroll
                    for (int k = 0; k < KK; k++) { e[k] = __expf(l[k] - t1); ssum += e[k]; }
                    float inv = 1.0f / ssum;
                    float2* lo2 = reinterpret_cast<float2*>(out_logit + (size_t)row * KK);
                    float2* qo2 = reinterpret_cast<float2*>(out_qy    + (size_t)row * KK);
                    #pragma unroll
                    for (int i = 0; i < KK / 2; i++) {
                        lo2[i] = make_float2(l[2 * i], l[2 * i + 1]);
                        qo2[i] = make_float2(e[2 * i] * inv, e[2 * i + 1] * inv);
                    }
                    int best = 0; float bv = l[0];
                    #pragma unroll
                    for (int k = 1; k < KK; k++) if (l[k] > bv) { bv = l[k]; best = k; }
                    out_ind[row] = (float)best;
                    int need = (!fast) | (t1 - t2 < MARGIN);
                    if (j == 0) needA = need; else needB = need;
                }
            }
        }

        // ---- warp-local exact fix via ballot (bits at lanes 8*grp) ----
        unsigned mA = __ballot_sync(0xffffffffu, needA);
        unsigned mB = __ballot_sync(0xffffffffu, needB);
        while (mA) {
            int b = __ffs(mA) - 1; mA &= mA - 1;
            fix_row(base + (b >> 3), lane, s_q[warp], s_nm, q, lv,
                    fast, logk, L2, out_logit, out_qy, out_ind);
        }
        while (mB) {
            int b = __ffs(mB) - 1; mB &= mB - 1;
            fix_row(base + 4 + (b >> 3), lane, s_q[warp], s_nm, q, lv,
                    fast, logk, L2, out_logit, out_qy, out_ind);
        }
    }
}

extern "C" void kernel_launch(void* const* d_in, const int* in_sizes, int n_in,
                              void* d_out, int out_size) {
    const float* q_z = (const float*)d_in[0];   // [B, 256]
    const float* mu  = (const float*)d_in[1];   // [10, 256]
    const float* lv  = (const float*)d_in[2];   // [10, 256]

    int nrows = in_sizes[0] / DD;

    float* out_logit = (float*)d_out;                    // [B, 10]
    float* out_qy    = out_logit + (size_t)nrows * KK;   // [B, 10]
    float* out_ind   = out_qy    + (size_t)nrows * KK;   // [B]

    k_all<<<NBLK, 128>>>(q_z, mu, lv, out_logit, out_qy, out_ind, nrows);
}

// round 17
// speedup vs baseline: 1.5984x; 1.5984x over previous
#include <cuda_runtime.h>
#include <cuda_bf16.h>
#include <cstdint>
#include <math.h>

// Problem constants (dataset: B=65536, D=256, K=10)
#define KK 10
#define DD 256
#define NBLK 148
#define TPB 512                // 16 warps
#define WPB 16
#define L2PI_F 1.8378770664093453f
#define MARGIN 0.02f

typedef unsigned long long ull;
typedef unsigned int uint;

// ---- dynamic smem layout (bytes) ----
#define SM_BFRAG 0            // uint4[16 kc][2 nt][32 lane] = 16384
#define SM_CBH   16384        // ushort[10][256] = 5120
#define SM_CBL   21504        // 5120
#define SM_NM    26624        // ull[1280] = 10240 (fix table, p*KK+k)
#define SM_A     36864        // per warp 4608B (hi 16x144, lo 16x144) x16 = 73728
#define SM_L     110592       // per warp 16x20 floats = 1280B x16 = 20480
#define SM_S2    131072       // per warp 16 floats x16 = 1024
#define SM_QFIX  132096       // per warp 128 ull = 1024B x16 = 16384
#define SM_C     148480       // 16 floats
#define SM_CPART 148544       // 80 floats = 320
#define SM_NZ    148864       // 4
#define SMEM_TOTAL 149504

// ---------- helpers ----------
static __device__ __forceinline__ ull pack2(float x, float y) {
    ull r; asm("mov.b64 %0, {%1, %2};" : "=l"(r) : "f"(x), "f"(y)); return r;
}
static __device__ __forceinline__ void unpack2(ull v, float& x, float& y) {
    asm("mov.b64 {%0, %1}, %2;" : "=f"(x), "=f"(y) : "l"(v));
}
static __device__ __forceinline__ ull add2(ull a, ull b) {
    ull d; asm("add.rn.f32x2 %0, %1, %2;" : "=l"(d) : "l"(a), "l"(b)); return d;
}
static __device__ __forceinline__ ull mul2(ull a, ull b) {
    ull d; asm("mul.rn.f32x2 %0, %1, %2;" : "=l"(d) : "l"(a), "l"(b)); return d;
}
// pack two f32 -> bf16x2 (lower = lo, upper = hi)
static __device__ __forceinline__ uint cvt2bf(float lo, float hi) {
    uint r; asm("cvt.rn.bf16x2.f32 %0, %1, %2;" : "=r"(r) : "f"(hi), "f"(lo));
    return r;
}
static __device__ __forceinline__ uint smem_u32(const void* p) {
    uint a; asm("{ .reg .u64 t; cvta.to.shared.u64 t, %1; cvt.u32.u64 %0, t; }"
                : "=r"(a) : "l"(p));
    return a;
}
static __device__ __forceinline__ void ldm_x4(uint& a0, uint& a1, uint& a2, uint& a3,
                                              uint addr) {
    asm volatile("ldmatrix.sync.aligned.m8n8.x4.shared.b16 {%0,%1,%2,%3}, [%4];"
                 : "=r"(a0), "=r"(a1), "=r"(a2), "=r"(a3) : "r"(addr));
}
static __device__ __forceinline__ void mma_bf16(float* c, const uint* a, uint b0, uint b1) {
    asm volatile(
        "mma.sync.aligned.m16n8k16.row.col.f32.bf16.bf16.f32 "
        "{%0,%1,%2,%3}, {%4,%5,%6,%7}, {%8,%9}, {%0,%1,%2,%3};"
        : "+f"(c[0]), "+f"(c[1]), "+f"(c[2]), "+f"(c[3])
        : "r"(a[0]), "r"(a[1]), "r"(a[2]), "r"(a[3]), "r"(b0), "r"(b1));
}

// ---- warp-collective exact fix for one row (bitwise XLA:GPU order, proven r11-15) ----
static __device__ __forceinline__ void fix_row(
    int rr, int lane, ull* sq, const ull* s_nm,
    const float* __restrict__ q, const float* __restrict__ lv,
    int fast, float logk, ull L2,
    float* out_logit, float* out_qy, float* out_ind)
{
    const int kk = (lane < 20) ? (lane >> 1) : 0;
    const int h  = lane & 1;
    {
        const float4* q4 = reinterpret_cast<const float4*>(q + (size_t)rr * DD);
        float4 v0 = __ldg(q4 + lane);
        float4 v1 = __ldg(q4 + lane + 32);
        sq[2 * lane]            = pack2(v0.x, v0.y);
        sq[2 * lane + 1]        = pack2(v0.z, v0.w);
        sq[2 * (lane + 32)]     = pack2(v1.x, v1.y);
        sq[2 * (lane + 32) + 1] = pack2(v1.z, v1.w);
    }
    __syncwarp();

    float Wv[2];
    #pragma unroll
    for (int t2 = 0; t2 < 2; t2++) {
        const int w4 = h + 2 * t2;
        float a[16];
        if (fast) {
            #pragma unroll
            for (int l = 0; l < 16; l++) {
                int p1 = w4 * 32 + l, p2 = p1 + 16;
                ull f1 = add2(sq[p1], s_nm[p1 * KK + kk]);
                ull u1 = add2(mul2(f1, f1), L2);
                ull f2 = add2(sq[p2], s_nm[p2 * KK + kk]);
                ull u2 = add2(mul2(f2, f2), L2);
                float x1, y1, x2, y2;
                unpack2(u1, x1, y1); unpack2(u2, x2, y2);
                a[l] = __fadd_rn(__fadd_rn(x1, y1), __fadd_rn(x2, y2));
            }
        } else {
            #pragma unroll
            for (int l = 0; l < 16; l++) {
                float s12[2];
                #pragma unroll
                for (int hh = 0; hh < 2; hh++) {
                    int p = w4 * 32 + l + 16 * hh;
                    float q0, q1, n0, n1;
                    unpack2(sq[p], q0, q1);
                    unpack2(s_nm[p * KK + kk], n0, n1);
                    float v0 = __ldg(&lv[kk * DD + 2 * p]);
                    float v1 = __ldg(&lv[kk * DD + 2 * p + 1]);
                    float e0 = (v0 == 0.0f) ? 1.0f : expf(v0);
                    float e1 = (v1 == 0.0f) ? 1.0f : expf(v1);
                    float f0 = __fadd_rn(q0, n0), f1 = __fadd_rn(q1, n1);
                    float u0 = __fadd_rn(__fadd_rn(
                        __fdiv_rn(__fmul_rn(f0, f0), e0), v0), L2PI_F);
                    float u1 = __fadd_rn(__fadd_rn(
                        __fdiv_rn(__fmul_rn(f1, f1), e1), v1), L2PI_F);
                    s12[hh] = __fadd_rn(u0, u1);
                }
                a[l] = __fadd_rn(s12[0], s12[1]);
            }
        }
        float bb[8];
        #pragma unroll
        for (int l = 0; l < 8; l++) bb[l] = __fadd_rn(a[l], a[l + 8]);
        float cc[4];
        #pragma unroll
        for (int l = 0; l < 4; l++) cc[l] = __fadd_rn(bb[l], bb[l + 4]);
        Wv[t2] = __fadd_rn(__fadd_rn(cc[0], cc[2]), __fadd_rn(cc[1], cc[3]));
    }
    float sum2 = __fadd_rn(Wv[0], Wv[1]);
    float s_other = __shfl_down_sync(0xffffffffu, sum2, 1);
    float L = __fadd_rn(sum2, s_other);
    float lgt = __fadd_rn(__fmul_rn(-0.5f, L), logk);

    float l10[KK];
    #pragma unroll
    for (int k = 0; k < KK; k++) l10[k] = __shfl_sync(0xffffffffu, lgt, 2 * k);

    if (lane == 0) {
        float m = l10[0];
        #pragma unroll
        for (int k = 1; k < KK; k++) m = fmaxf(m, l10[k]);
        float e[KK];
        #pragma unroll
        for (int k = 0; k < KK; k++) e[k] = expf(__fadd_rn(l10[k], -m));
        float s0 = __fadd_rn(__fadd_rn(__fadd_rn(e[0], e[8]), e[4]),
                             __fadd_rn(e[2], e[6]));
        float s1 = __fadd_rn(__fadd_rn(__fadd_rn(e[1], e[9]), e[5]),
                             __fadd_rn(e[3], e[7]));
        float ssum = __fadd_rn(s0, s1);
        float qv[KK];
        #pragma unroll
        for (int k = 0; k < KK; k++) qv[k] = __fdiv_rn(e[k], ssum);
        #pragma unroll
        for (int k = 0; k < KK; k++) {
            out_logit[(size_t)rr * KK + k] = l10[k];
            out_qy   [(size_t)rr * KK + k] = qv[k];
        }
        int best = 0; float bv = qv[0];
        #pragma unroll
        for (int k = 1; k < KK; k++) if (qv[k] > bv) { bv = qv[k]; best = k; }
        out_ind[rr] = (float)best;
    }
    __syncwarp();
}

// ================== fused HMMA kernel ==================
__global__ void __launch_bounds__(TPB, 1)
k_all(const float* __restrict__ q, const float* __restrict__ mu,
      const float* __restrict__ lv,
      float* __restrict__ out_logit, float* __restrict__ out_qy,
      float* __restrict__ out_ind, int nrows)
{
    extern __shared__ __align__(16) char smem[];
    uint4*  s_bfrag = reinterpret_cast<uint4*>(smem + SM_BFRAG);
    unsigned short* s_cbh = reinterpret_cast<unsigned short*>(smem + SM_CBH);
    unsigned short* s_cbl = reinterpret_cast<unsigned short*>(smem + SM_CBL);
    ull*    s_nm   = reinterpret_cast<ull*>(smem + SM_NM);
    float*  s_C    = reinterpret_cast<float*>(smem + SM_C);
    float*  s_Cp   = reinterpret_cast<float*>(smem + SM_CPART);
    int*    s_nz   = reinterpret_cast<int*>(smem + SM_NZ);

    const int t = threadIdx.x;
    const int lane = t & 31, warp = t >> 5;
    if (t == 0) *s_nz = 0;
    __syncthreads();

    // ---------- prep phase 1: cb hi/lo, fix table, C partials ----------
    int any = 0;
    #pragma unroll
    for (int i = 0; i < 5; i++) {
        int idx = t + TPB * i;               // 0..2559
        int k = idx >> 8, d = idx & 255;
        float l = lv[k * DD + d], m = mu[k * DD + d];
        float cb = -2.0f * __expf(-l) * m;
        uint wh = cvt2bf(cb, 0.0f);
        float cbh_f = __uint_as_float(wh << 16);
        uint wl = cvt2bf(cb - cbh_f, 0.0f);
        s_cbh[idx] = (unsigned short)(wh & 0xFFFFu);
        s_cbl[idx] = (unsigned short)(wl & 0xFFFFu);
        if (l != 0.0f) any = 1;
    }
    #pragma unroll
    for (int i = 0; i < 3; i++) {
        int ix = t + TPB * i;
        if (ix < 128 * KK) {
            int p = ix / KK, k = ix % KK, d = 2 * p;
            s_nm[p * KK + k] = pack2(-mu[k * DD + d], -mu[k * DD + d + 1]);
        }
    }
    if (any) atomicOr(s_nz, 1);
    if (t < 80) {
        int k = t >> 3, part = t & 7;
        float s = 0.0f;
        #pragma unroll 4
        for (int j = 0; j < 32; j++) {
            int d = part * 32 + j;
            float l = lv[k * DD + d], m = mu[k * DD + d];
            s += __fmaf_rn(__expf(-l) * m, m, l) + L2PI_F;
        }
        s_Cp[k * 8 + part] = s;
    }
    __syncthreads();

    // ---------- prep phase 2: B fragments + C ----------
    #pragma unroll
    for (int i = 0; i < 2; i++) {
        int e = t + TPB * i;                 // 0..1023
        int ln = e & 31, nt = (e >> 5) & 1, kc = e >> 6;
        int gid = ln >> 2, tig = ln & 3;
        int n = nt * 8 + gid;
        uint4 val = make_uint4(0u, 0u, 0u, 0u);
        if (n < KK) {
            int kb = kc * 16;
            uint h0 = (uint)s_cbh[n * DD + kb + 2 * tig]
                    | ((uint)s_cbh[n * DD + kb + 2 * tig + 1] << 16);
            uint h1 = (uint)s_cbh[n * DD + kb + 2 * tig + 8]
                    | ((uint)s_cbh[n * DD + kb + 2 * tig + 9] << 16);
            uint l0 = (uint)s_cbl[n * DD + kb + 2 * tig]
                    | ((uint)s_cbl[n * DD + kb + 2 * tig + 1] << 16);
            uint l1 = (uint)s_cbl[n * DD + kb + 2 * tig + 8]
                    | ((uint)s_cbl[n * DD + kb + 2 * tig + 9] << 16);
            val = make_uint4(h0, h1, l0, l1);
        }
        s_bfrag[(kc * 2 + nt) * 32 + ln] = val;
    }
    if (t < KK) {
        float tot = 0.0f;
        #pragma unroll
        for (int j = 0; j < 8; j++) tot += s_Cp[t * 8 + j];
        float logk0 = (float)log((double)(1.0f / (float)KK));
        s_C[t] = __fmaf_rn(-0.5f, tot, logk0);
    }
    __syncthreads();

    const int fast = (*s_nz == 0);
    const float logk = (float)log((double)(1.0f / (float)KK));
    const ull L2 = pack2(L2PI_F, L2PI_F);

    const uint sb = smem_u32(smem);
    const uint warpA = sb + SM_A + warp * 4608;        // hi tile; lo at +2304
    float* s_Lw  = reinterpret_cast<float*>(smem + SM_L)  + warp * 320;  // [16][20]
    float* s_S2w = reinterpret_cast<float*>(smem + SM_S2) + warp * 16;
    ull*   sq    = reinterpret_cast<ull*>(smem + SM_QFIX) + warp * 128;

    const int ntiles = (nrows + 15) / 16;
    const int f4col  = lane & 15;
    const int rhalf  = lane >> 4;            // 0 or 1

    // ldmatrix lane address components
    const int lseg  = lane >> 3;
    const int lrow  = (lane & 7) + 8 * (lseg & 1);
    const uint lhoff = (uint)((lseg >> 1) * 16);

    for (int tile = blockIdx.x + gridDim.x * warp; tile < ntiles;
         tile += gridDim.x * WPB) {
        const int rowbase = tile * 16;

        // tail tile (only if nrows % 16): exact path for all valid rows
        if (rowbase + 16 > nrows) {
            for (int r = 0; r < 16; r++) {
                int rr = rowbase + r;
                if (rr < nrows)
                    fix_row(rr, lane, sq, s_nm, q, lv, fast, logk, L2,
                            out_logit, out_qy, out_ind);
            }
            continue;
        }

        float acc0[4] = {0.f, 0.f, 0.f, 0.f};
        float acc1[4] = {0.f, 0.f, 0.f, 0.f};
        float s2p[8] = {0.f, 0.f, 0.f, 0.f, 0.f, 0.f, 0.f, 0.f};
        const float4* q4 = reinterpret_cast<const float4*>(q) + (size_t)rowbase * 64;

        #pragma unroll
        for (int chunk = 0; chunk < 4; chunk++) {
            // load + convert + stage (two batches of 4 float4)
            #pragma unroll
            for (int half = 0; half < 2; half++) {
                float4 v[4];
                #pragma unroll
                for (int j = 0; j < 4; j++) {
                    int jj = half * 4 + j;
                    int row = rhalf + 2 * jj;
                    v[j] = __ldg(q4 + row * 64 + chunk * 16 + f4col);
                }
                #pragma unroll
                for (int j = 0; j < 4; j++) {
                    int jj = half * 4 + j;
                    int row = rhalf + 2 * jj;
                    float f0 = v[j].x, f1 = v[j].y, f2 = v[j].z, f3 = v[j].w;
                    uint wh0 = cvt2bf(f0, f1);
                    uint wh1 = cvt2bf(f2, f3);
                    float h0 = __uint_as_float(wh0 << 16);
                    float h1 = __uint_as_float(wh0 & 0xFFFF0000u);
                    float h2 = __uint_as_float(wh1 << 16);
                    float h3 = __uint_as_float(wh1 & 0xFFFF0000u);
                    uint wl0 = cvt2bf(f0 - h0, f1 - h1);
                    uint wl1 = cvt2bf(f2 - h2, f3 - h3);
                    uint addr = warpA + (uint)(row * 144 + f4col * 8);
                    asm volatile("st.shared.v2.b32 [%0], {%1,%2};"
                                 :: "r"(addr), "r"(wh0), "r"(wh1) : "memory");
                    asm volatile("st.shared.v2.b32 [%0], {%1,%2};"
                                 :: "r"(addr + 2304u), "r"(wl0), "r"(wl1) : "memory");
                    s2p[jj] = __fmaf_rn(f0, f0, s2p[jj]);
                    s2p[jj] = __fmaf_rn(f1, f1, s2p[jj]);
                    s2p[jj] = __fmaf_rn(f2, f2, s2p[jj]);
                    s2p[jj] = __fmaf_rn(f3, f3, s2p[jj]);
                }
            }
            __syncwarp();

            // MMA: 4 k16 sub-steps
            #pragma unroll
            for (int sub = 0; sub < 4; sub++) {
                uint laddr = warpA + (uint)(lrow * 144 + sub * 32) + lhoff;
                uint ahi[4], alo[4];
                ldm_x4(ahi[0], ahi[1], ahi[2], ahi[3], laddr);
                ldm_x4(alo[0], alo[1], alo[2], alo[3], laddr + 2304u);
                int kc = chunk * 4 + sub;
                uint4 f0 = s_bfrag[(kc * 2 + 0) * 32 + lane];
                uint4 f1 = s_bfrag[(kc * 2 + 1) * 32 + lane];
                mma_bf16(acc0, ahi, f0.x, f0.y);
                mma_bf16(acc0, alo, f0.x, f0.y);
                mma_bf16(acc0, ahi, f0.z, f0.w);
                mma_bf16(acc1, ahi, f1.x, f1.y);
                mma_bf16(acc1, alo, f1.x, f1.y);
                mma_bf16(acc1, ahi, f1.z, f1.w);
            }
            __syncwarp();
        }

        // S2 reduce across 16-lane halves (cheap path, any order)
        #pragma unroll
        for (int off = 1; off < 16; off <<= 1) {
            #pragma unroll
            for (int j = 0; j < 8; j++)
                s2p[j] += __shfl_xor_sync(0xffffffffu, s2p[j], off);
        }
        if ((lane & 15) == 0) {
            #pragma unroll
            for (int j = 0; j < 8; j++) s_S2w[2 * j + rhalf] = s2p[j];
        }

        // scatter accumulators to s_L [16][20]
        {
            int r0 = lane >> 2, c0 = 2 * (lane & 3);
            *reinterpret_cast<float2*>(s_Lw + r0 * 20 + c0)
                = make_float2(acc0[0], acc0[1]);
            *reinterpret_cast<float2*>(s_Lw + (r0 + 8) * 20 + c0)
                = make_float2(acc0[2], acc0[3]);
            if ((lane & 3) == 0) {
                *reinterpret_cast<float2*>(s_Lw + r0 * 20 + 8)
                    = make_float2(acc1[0], acc1[1]);
                *reinterpret_cast<float2*>(s_Lw + (r0 + 8) * 20 + 8)
                    = make_float2(acc1[2], acc1[3]);
            }
        }
        __syncwarp();

        // ---- cheap finish: lanes 0-15, one row each ----
        int need = 0;
        if (lane < 16) {
            const int row = rowbase + lane;
            float s2 = s_S2w[lane];
            float l[KK];
            #pragma unroll
            for (int k = 0; k < KK; k++)
                l[k] = __fmaf_rn(-0.5f, s_Lw[lane * 20 + k] + s2, s_C[k]);
            float t1 = l[0], t2 = -3.4e38f;
            #pragma unroll
            for (int k = 1; k < KK; k++) {
                float v = l[k];
                if (v > t1) { t2 = t1; t1 = v; } else if (v > t2) t2 = v;
            }
            float e[KK], ssum = 0.0f;
            #pragma unroll
            for (int k = 0; k < KK; k++) { e[k] = __expf(l[k] - t1); ssum += e[k]; }
            float inv = 1.0f / ssum;
            float2* lo2 = reinterpret_cast<float2*>(out_logit + (size_t)row * KK);
            float2* qo2 = reinterpret_cast<float2*>(out_qy    + (size_t)row * KK);
            #pragma unroll
            for (int i = 0; i < KK / 2; i++) {
                lo2[i] = make_float2(l[2 * i], l[2 * i + 1]);
                qo2[i] = make_float2(e[2 * i] * inv, e[2 * i + 1] * inv);
            }
            int best = 0; float bv = l[0];
            #pragma unroll
            for (int k = 1; k < KK; k++) if (l[k] > bv) { bv = l[k]; best = k; }
            out_ind[row] = (float)best;
            need = (!fast) | (t1 - t2 < MARGIN);
        }

        // ---- warp-local exact fix via ballot ----
        unsigned mask = __ballot_sync(0xffffffffu, need);
        while (mask) {
            int b = __ffs(mask) - 1; mask &= mask - 1;
            fix_row(rowbase + b, lane, sq, s_nm, q, lv, fast, logk, L2,
                    out_logit, out_qy, out_ind);
        }
    }
}

extern "C" void kernel_launch(void* const* d_in, const int* in_sizes, int n_in,
                              void* d_out, int out_size) {
    const float* q_z = (const float*)d_in[0];   // [B, 256]
    const float* mu  = (const float*)d_in[1];   // [10, 256]
    const float* lv  = (const float*)d_in[2];   // [10, 256]

    int nrows = in_sizes[0] / DD;

    float* out_logit = (float*)d_out;                    // [B, 10]
    float* out_qy    = out_logit + (size_t)nrows * KK;   // [B, 10]
    float* out_ind   = out_qy    + (size_t)nrows * KK;   // [B]

    cudaFuncSetAttribute(k_all, cudaFuncAttributeMaxDynamicSharedMemorySize,
                         SMEM_TOTAL);
    k_all<<<NBLK, TPB, SMEM_TOTAL>>>(q_z, mu, lv, out_logit, out_qy, out_ind, nrows);
}